// round 2
// baseline (speedup 1.0000x reference)
#include <cuda_runtime.h>

// ---------------------------------------------------------------------------
// 3-layer GCN:  h = X@W ; agg = scatter_add(h[src]*coef -> dst) + h/deg + b
// coef = rsqrt(deg[src]) * rsqrt(deg[dst]),  deg = in-degree(dst) + 1
// Layers: 128->128 (relu), 128->128 (relu), 128->64
// NOTE: edge_index is int32 (JAX x64 disabled downcasts int64 -> int32).
// ---------------------------------------------------------------------------

#define NN 50000
#define EE 640000

// scratch (device globals: allocation-free per harness rules)
__device__ float g_h[NN * 128];     // per-layer linear output
__device__ float g_agg1[NN * 128];  // layer-1 aggregate
__device__ float g_agg2[NN * 128];  // layer-2 aggregate
__device__ float g_deg[NN];
__device__ float g_dis[NN];         // deg^-1/2
__device__ float g_dinv[NN];        // deg^-1

// ---------------------------------------------------------------------------
__global__ void k_deg_init(float* deg, int n) {
    int i = blockIdx.x * blockDim.x + threadIdx.x;
    if (i < n) deg[i] = 1.0f;
}

__global__ void k_deg_count(const int* __restrict__ dst, float* deg, int e) {
    int i = blockIdx.x * blockDim.x + threadIdx.x;
    if (i < e) atomicAdd(&deg[dst[i]], 1.0f);
}

__global__ void k_deg_fin(const float* __restrict__ deg, float* dis, float* dinv, int n) {
    int i = blockIdx.x * blockDim.x + threadIdx.x;
    if (i < n) {
        float d = deg[i];
        dis[i]  = rsqrtf(d);
        dinv[i] = 1.0f / d;
    }
}

// ---------------------------------------------------------------------------
// GEMM: H[nrows,C] = act(X)[nrows,128] @ W[128,C]
// Epilogue also writes AGG = H * dinv[row] + bias  (self-loop + bias init)
// Register blocking 4x4, K-tiled through shared memory.
// ---------------------------------------------------------------------------
template <int C, bool RELU>
__global__ void __launch_bounds__(256) k_gemm(
    const float* __restrict__ X, const float* __restrict__ W,
    const float* __restrict__ bias, const float* __restrict__ dinv,
    float* __restrict__ H, float* __restrict__ AGG, int nrows)
{
    constexpr int CG = C / 4;        // thread groups along columns
    constexpr int RG = 256 / CG;     // thread groups along rows
    constexpr int MT = RG * 4;       // rows per block
    constexpr int KT = 32;           // k tile
    constexpr int K4 = KT / 4;       // float4s per row per k-tile

    __shared__ __align__(16) float Xs[KT][MT + 4];  // k-major
    __shared__ __align__(16) float Ws[KT][C];

    const int t  = threadIdx.x;
    const int cx = t % CG;
    const int ry = t / CG;
    const int m0 = blockIdx.x * MT;

    float acc[4][4] = {};

    for (int k0 = 0; k0 < 128; k0 += KT) {
        // load X tile (transposed into k-major smem), optional relu
        {
            constexpr int L = (MT * K4) / 256;
            #pragma unroll
            for (int l = 0; l < L; l++) {
                int idx = t + l * 256;
                int row = idx / K4;
                int j   = idx % K4;
                float4 v = make_float4(0.f, 0.f, 0.f, 0.f);
                if (m0 + row < nrows)
                    v = *(const float4*)&X[(m0 + row) * 128 + k0 + j * 4];
                if (RELU) {
                    v.x = fmaxf(v.x, 0.f); v.y = fmaxf(v.y, 0.f);
                    v.z = fmaxf(v.z, 0.f); v.w = fmaxf(v.w, 0.f);
                }
                Xs[j * 4 + 0][row] = v.x;
                Xs[j * 4 + 1][row] = v.y;
                Xs[j * 4 + 2][row] = v.z;
                Xs[j * 4 + 3][row] = v.w;
            }
        }
        // load W tile
        {
            constexpr int L = (KT * CG) / 256;
            #pragma unroll
            for (int l = 0; l < L; l++) {
                int idx = t + l * 256;
                int k   = idx / CG;
                int cq  = idx % CG;
                *(float4*)&Ws[k][cq * 4] =
                    *(const float4*)&W[(k0 + k) * C + cq * 4];
            }
        }
        __syncthreads();

        #pragma unroll
        for (int k = 0; k < KT; k++) {
            float4 xv = *(const float4*)&Xs[k][ry * 4];
            float4 wv = *(const float4*)&Ws[k][cx * 4];
            float xr[4] = {xv.x, xv.y, xv.z, xv.w};
            float wr[4] = {wv.x, wv.y, wv.z, wv.w};
            #pragma unroll
            for (int i = 0; i < 4; i++)
                #pragma unroll
                for (int j = 0; j < 4; j++)
                    acc[i][j] = fmaf(xr[i], wr[j], acc[i][j]);
        }
        __syncthreads();
    }

    float4 bv = *(const float4*)&bias[cx * 4];
    #pragma unroll
    for (int i = 0; i < 4; i++) {
        int row = m0 + ry * 4 + i;
        if (row < nrows) {
            float di = dinv[row];
            float4 hv = make_float4(acc[i][0], acc[i][1], acc[i][2], acc[i][3]);
            *(float4*)&H[row * C + cx * 4] = hv;
            float4 av = make_float4(fmaf(hv.x, di, bv.x), fmaf(hv.y, di, bv.y),
                                    fmaf(hv.z, di, bv.z), fmaf(hv.w, di, bv.w));
            *(float4*)&AGG[row * C + cx * 4] = av;
        }
    }
}

// ---------------------------------------------------------------------------
// Edge scatter:  AGG[dst] += H[src] * dis[src]*dis[dst]
// One edge per (C/4)-lane group; vector float4 atomics (sm_90+ red.v4).
// ---------------------------------------------------------------------------
template <int C>
__global__ void __launch_bounds__(256) k_scatter(
    const int* __restrict__ src, const int* __restrict__ dst,
    const float* __restrict__ H, const float* __restrict__ dis,
    float* __restrict__ AGG, int ne)
{
    constexpr int LPE = C / 4;       // lanes per edge
    constexpr int EPB = 256 / LPE;   // edges per block
    int e    = blockIdx.x * EPB + threadIdx.x / LPE;
    int lane = threadIdx.x % LPE;
    if (e >= ne) return;

    int s = src[e];
    int d = dst[e];
    float coef = dis[s] * dis[d];

    float4 v = *(const float4*)&H[s * C + lane * 4];
    float4 out = make_float4(v.x * coef, v.y * coef, v.z * coef, v.w * coef);
    atomicAdd(reinterpret_cast<float4*>(&AGG[d * C + lane * 4]), out);
}

// ---------------------------------------------------------------------------
extern "C" void kernel_launch(void* const* d_in, const int* in_sizes, int n_in,
                              void* d_out, int out_size)
{
    const float* x  = (const float*)d_in[0];
    const int*   ei = (const int*)d_in[1];
    const float* W1 = (const float*)d_in[2];
    const float* b1 = (const float*)d_in[3];
    const float* W2 = (const float*)d_in[4];
    const float* b2 = (const float*)d_in[5];
    const float* W3 = (const float*)d_in[6];
    const float* b3 = (const float*)d_in[7];
    float* out = (float*)d_out;

    const int E = in_sizes[1] / 2;
    const int N = in_sizes[0] / 128;
    const int* src = ei;
    const int* dst = ei + E;

    float *ph, *pa1, *pa2, *pdeg, *pdis, *pdinv;
    cudaGetSymbolAddress((void**)&ph,    g_h);
    cudaGetSymbolAddress((void**)&pa1,   g_agg1);
    cudaGetSymbolAddress((void**)&pa2,   g_agg2);
    cudaGetSymbolAddress((void**)&pdeg,  g_deg);
    cudaGetSymbolAddress((void**)&pdis,  g_dis);
    cudaGetSymbolAddress((void**)&pdinv, g_dinv);

    // degree / normalization (shared by all layers)
    k_deg_init<<<(N + 255) / 256, 256>>>(pdeg, N);
    k_deg_count<<<(E + 255) / 256, 256>>>(dst, pdeg, E);
    k_deg_fin<<<(N + 255) / 256, 256>>>(pdeg, pdis, pdinv, N);

    // layer 1: x -> agg1   (relu folded into layer-2 input load)
    k_gemm<128, false><<<(N + 31) / 32, 256>>>(x, W1, b1, pdinv, ph, pa1, N);
    k_scatter<128><<<(E + 7) / 8, 256>>>(src, dst, ph, pdis, pa1, E);

    // layer 2: relu(agg1) -> agg2
    k_gemm<128, true><<<(N + 31) / 32, 256>>>(pa1, W2, b2, pdinv, ph, pa2, N);
    k_scatter<128><<<(E + 7) / 8, 256>>>(src, dst, ph, pdis, pa2, E);

    // layer 3: relu(agg2) -> out (C=64), no output relu
    k_gemm<64, true><<<(N + 63) / 64, 256>>>(pa2, W3, b3, pdinv, ph, out, N);
    k_scatter<64><<<(E + 15) / 16, 256>>>(src, dst, ph, pdis, out, E);
}